// round 1
// baseline (speedup 1.0000x reference)
#include <cuda_runtime.h>
#include <math.h>

// Problem constants
#define SLEN 2048
#define DDIM 128
#define NBATCH 16
#define TQ 64
#define TK 64
#define THREADS 256

#define QSTR 132   // padded smem row stride (floats) for Q/K/V tiles
#define PSTR 68    // padded smem row stride for probability tile

// smem layout (floats)
#define SQ_OFF 0
#define SK_OFF (SQ_OFF + TQ * QSTR)
#define SV_OFF (SK_OFF + TK * QSTR)
#define SP_OFF (SV_OFF + TK * QSTR)
#define SL_OFF (SP_OFF + TQ * PSTR)
#define SMEM_FLOATS (SL_OFF + TQ)
#define SMEM_BYTES (SMEM_FLOATS * 4)

__global__ __launch_bounds__(THREADS, 1)
void attn_fp32_kernel(const float* __restrict__ Qg,
                      const float* __restrict__ Tg,
                      const float* __restrict__ Vg,
                      float* __restrict__ Og) {
    extern __shared__ float smem[];
    float* sQ = smem + SQ_OFF;
    float* sK = smem + SK_OFF;
    float* sV = smem + SV_OFF;
    float* sP = smem + SP_OFF;
    float* sL = smem + SL_OFF;

    const int b  = blockIdx.y;
    const int qt = (gridDim.x - 1) - blockIdx.x;   // heavy tiles first
    const int tid = threadIdx.x;
    const int warp = tid >> 5;
    const int lane = tid & 31;
    const float inv_sqrt_d = 0.08838834764831845f; // 1/sqrt(128)

    // ---- load Q tile (64 x 128) into smem, float4 coalesced ----
    {
        const float4* src = (const float4*)(Qg + ((size_t)b * SLEN + (size_t)qt * TQ) * DDIM);
        #pragma unroll
        for (int it = 0; it < (TQ * (DDIM / 4)) / THREADS; it++) {
            int i = it * THREADS + tid;
            int r = i >> 5;           // /32 chunks per row
            int c = i & 31;
            ((float4*)(sQ + r * QSTR))[c] = src[r * (DDIM / 4) + c];
        }
    }
    if (tid < TQ) sL[tid] = 0.0f;

    // PV mapping: warp -> 8 rows, lane -> cols {lane, lane+32, lane+64, lane+96}
    float acc[8][4];
    #pragma unroll
    for (int r = 0; r < 8; r++)
        #pragma unroll
        for (int c = 0; c < 4; c++) acc[r][c] = 0.0f;

    // Score mapping: rg = tid/16 (4 rows), cg = tid%16, cols {cg+16*j}
    const int rg = tid >> 4;
    const int cg = tid & 15;

    for (int kt = 0; kt <= qt; kt++) {
        __syncthreads();  // previous PV done before overwriting K/V

        // ---- load K,V tiles ----
        {
            const float4* ks = (const float4*)(Tg + ((size_t)b * SLEN + (size_t)kt * TK) * DDIM);
            const float4* vs = (const float4*)(Vg + ((size_t)b * SLEN + (size_t)kt * TK) * DDIM);
            #pragma unroll
            for (int it = 0; it < (TK * (DDIM / 4)) / THREADS; it++) {
                int i = it * THREADS + tid;
                int r = i >> 5;
                int c = i & 31;
                ((float4*)(sK + r * QSTR))[c] = ks[r * (DDIM / 4) + c];
                ((float4*)(sV + r * QSTR))[c] = vs[r * (DDIM / 4) + c];
            }
        }
        __syncthreads();

        // ---- scores: 4x4 register tile, QK^T over d=128 ----
        float s[4][4];
        #pragma unroll
        for (int i = 0; i < 4; i++)
            #pragma unroll
            for (int j = 0; j < 4; j++) s[i][j] = 0.0f;

        const float4* qrow0 = (const float4*)(sQ + (rg * 4 + 0) * QSTR);
        const float4* qrow1 = (const float4*)(sQ + (rg * 4 + 1) * QSTR);
        const float4* qrow2 = (const float4*)(sQ + (rg * 4 + 2) * QSTR);
        const float4* qrow3 = (const float4*)(sQ + (rg * 4 + 3) * QSTR);
        const float4* krow0 = (const float4*)(sK + (cg +  0) * QSTR);
        const float4* krow1 = (const float4*)(sK + (cg + 16) * QSTR);
        const float4* krow2 = (const float4*)(sK + (cg + 32) * QSTR);
        const float4* krow3 = (const float4*)(sK + (cg + 48) * QSTR);

        #pragma unroll 8
        for (int d4 = 0; d4 < DDIM / 4; d4++) {
            float4 qv[4], kv[4];
            qv[0] = qrow0[d4]; qv[1] = qrow1[d4]; qv[2] = qrow2[d4]; qv[3] = qrow3[d4];
            kv[0] = krow0[d4]; kv[1] = krow1[d4]; kv[2] = krow2[d4]; kv[3] = krow3[d4];
            #pragma unroll
            for (int i = 0; i < 4; i++) {
                #pragma unroll
                for (int j = 0; j < 4; j++) {
                    s[i][j] += qv[i].x * kv[j].x;
                    s[i][j] += qv[i].y * kv[j].y;
                    s[i][j] += qv[i].z * kv[j].z;
                    s[i][j] += qv[i].w * kv[j].w;
                }
            }
        }

        // ---- threshold + causal + exp, write p to smem, row partial sums ----
        const bool diag = (kt == qt);
        float rowsum[4];
        #pragma unroll
        for (int i = 0; i < 4; i++) {
            const int lr = rg * 4 + i;   // local row
            float psum = 0.0f;
            #pragma unroll
            for (int j = 0; j < 4; j++) {
                const int lc = cg + 16 * j;  // local col
                float sv = s[i][j];
                float lg = (sv > 0.3f) ? sv * inv_sqrt_d : 0.0f;
                float pe = __expf(lg);
                if (diag && (lc > lr)) pe = 0.0f;
                sP[lr * PSTR + lc] = pe;
                psum += pe;
            }
            rowsum[i] = psum;
        }
        // reduce across the 16 lanes sharing this row group (stays in half-warp)
        #pragma unroll
        for (int off = 8; off >= 1; off >>= 1) {
            #pragma unroll
            for (int i = 0; i < 4; i++)
                rowsum[i] += __shfl_xor_sync(0xffffffffu, rowsum[i], off);
        }
        if (cg == 0) {
            #pragma unroll
            for (int i = 0; i < 4; i++) sL[rg * 4 + i] += rowsum[i];
        }
        __syncthreads();

        // ---- PV accumulate: acc[r][c] += sum_j p[r][j] * V[j][c] ----
        #pragma unroll 4
        for (int j = 0; j < TK; j++) {
            const float* vrow = sV + j * QSTR + lane;
            float v0 = vrow[0];
            float v1 = vrow[32];
            float v2 = vrow[64];
            float v3 = vrow[96];
            const float* prow = sP + (warp * 8) * PSTR + j;
            #pragma unroll
            for (int r = 0; r < 8; r++) {
                float pr = prow[r * PSTR];   // broadcast across lanes
                acc[r][0] += pr * v0;
                acc[r][1] += pr * v1;
                acc[r][2] += pr * v2;
                acc[r][3] += pr * v3;
            }
        }
    }

    __syncthreads();

    // ---- normalize and store ----
    float* out = Og + ((size_t)b * SLEN + (size_t)qt * TQ) * DDIM;
    #pragma unroll
    for (int r = 0; r < 8; r++) {
        const int row = warp * 8 + r;
        const float invl = 1.0f / sL[row];
        out[row * DDIM + lane +  0] = acc[r][0] * invl;
        out[row * DDIM + lane + 32] = acc[r][1] * invl;
        out[row * DDIM + lane + 64] = acc[r][2] * invl;
        out[row * DDIM + lane + 96] = acc[r][3] * invl;
    }
}

extern "C" void kernel_launch(void* const* d_in, const int* in_sizes, int n_in,
                              void* d_out, int out_size) {
    (void)in_sizes; (void)n_in; (void)out_size;
    const float* Q = (const float*)d_in[0];
    const float* T = (const float*)d_in[1];
    const float* V = (const float*)d_in[2];
    float* O = (float*)d_out;

    cudaFuncSetAttribute(attn_fp32_kernel,
                         cudaFuncAttributeMaxDynamicSharedMemorySize, SMEM_BYTES);

    dim3 grid(SLEN / TQ, NBATCH);
    attn_fp32_kernel<<<grid, THREADS, SMEM_BYTES>>>(Q, T, V, O);
}

// round 4
// speedup vs baseline: 1.0626x; 1.0626x over previous
#include <cuda_runtime.h>
#include <cstdint>

#define SLEN 2048
#define DDIM 128
#define NB 16
#define TQ 128
#define TK 64
#define THREADS 256

// padded smem strides (floats); all chosen conflict-free for fragment patterns
#define QSTR 132
#define KSTR 132
#define VSTR 136
#define PSTR 68

// smem layout (float offsets)
#define SQ_OFF 0
#define SK_OFF (SQ_OFF + TQ * QSTR)        // 16896
#define SV_OFF (SK_OFF + TK * KSTR)        // 25344
#define SP_OFF (SV_OFF + TK * VSTR)        // 34048
#define SRS_OFF (SP_OFF + TQ * PSTR)       // 42752
#define SMEM_FLOATS (SRS_OFF + 2 * TQ)
#define SMEM_BYTES (SMEM_FLOATS * 4)       // 172032 B

__device__ __forceinline__ float cvt_tf32(float x) {
    float r; asm("cvt.rna.tf32.f32 %0, %1;" : "=f"(r) : "f"(x)); return r;
}
__device__ __forceinline__ void split_tf32(float x, uint32_t& hi, uint32_t& lo) {
    float h = cvt_tf32(x);
    float l = cvt_tf32(x - h);
    hi = __float_as_uint(h);
    lo = __float_as_uint(l);
}
__device__ __forceinline__ void mma8(float* d,
                                     uint32_t a0, uint32_t a1, uint32_t a2, uint32_t a3,
                                     uint32_t b0, uint32_t b1) {
    asm volatile("mma.sync.aligned.m16n8k8.row.col.f32.tf32.tf32.f32 "
                 "{%0,%1,%2,%3}, {%4,%5,%6,%7}, {%8,%9}, {%0,%1,%2,%3};"
                 : "+f"(d[0]), "+f"(d[1]), "+f"(d[2]), "+f"(d[3])
                 : "r"(a0), "r"(a1), "r"(a2), "r"(a3), "r"(b0), "r"(b1));
}

__global__ __launch_bounds__(THREADS, 1)
void attn_mma(const float* __restrict__ Qg, const float* __restrict__ Tg,
              const float* __restrict__ Vg, float* __restrict__ Og) {
    extern __shared__ float sm[];
    float* sQ = sm + SQ_OFF;
    float* sK = sm + SK_OFF;
    float* sV = sm + SV_OFF;
    float* sP = sm + SP_OFF;
    float* sRS = sm + SRS_OFF;

    const int b = blockIdx.y;
    const int qt = (gridDim.x - 1) - blockIdx.x;    // heavy q-tiles first
    const int tid = threadIdx.x;
    const int warp = tid >> 5, lane = tid & 31;
    const int lq = lane >> 2;        // quad row 0..7
    const int lr = lane & 3;         // lane-in-quad 0..3
    const int wr = (warp & 3) * 32;  // warp q-row base (2 m-tiles)
    const int wcS = (warp >> 2) * 32;   // QK col base (4 n-tiles)
    const int wcO = (warp >> 2) * 64;   // PV col base (8 n-tiles)
    const float ISD = 0.08838834764831845f;  // 1/sqrt(128)

    // ---- load Q tile (raw f32) ----
    {
        const float4* src = (const float4*)(Qg + ((size_t)b * SLEN + (size_t)qt * TQ) * DDIM);
        #pragma unroll
        for (int it = 0; it < 16; it++) {
            int i = it * THREADS + tid;
            int r = i >> 5, j = i & 31;
            *(float4*)(sQ + r * QSTR + 4 * j) = src[(size_t)r * 32 + j];
        }
    }

    float Oa[2][8][4];
    #pragma unroll
    for (int mt = 0; mt < 2; mt++)
        #pragma unroll
        for (int nt = 0; nt < 8; nt++)
            #pragma unroll
            for (int k = 0; k < 4; k++) Oa[mt][nt][k] = 0.0f;
    float rs[2][2] = {{0.0f, 0.0f}, {0.0f, 0.0f}};

    const int nkt = 2 * qt + 2;
    for (int kt = 0; kt < nkt; kt++) {
        __syncthreads();   // previous PV reads done before overwriting K/V

        // ---- load K,V tiles (raw f32) ----
        {
            const float4* ks = (const float4*)(Tg + ((size_t)b * SLEN + (size_t)kt * TK) * DDIM);
            const float4* vs = (const float4*)(Vg + ((size_t)b * SLEN + (size_t)kt * TK) * DDIM);
            #pragma unroll
            for (int it = 0; it < 8; it++) {
                int i = it * THREADS + tid;
                int r = i >> 5, j = i & 31;
                *(float4*)(sK + r * KSTR + 4 * j) = ks[(size_t)r * 32 + j];
                *(float4*)(sV + r * VSTR + 4 * j) = vs[(size_t)r * 32 + j];
            }
        }
        __syncthreads();

        // ---- QK^T: 3xTF32, warp tile 32 rows x 32 cols ----
        float S[2][4][4];
        #pragma unroll
        for (int mt = 0; mt < 2; mt++)
            #pragma unroll
            for (int nt = 0; nt < 4; nt++)
                #pragma unroll
                for (int k = 0; k < 4; k++) S[mt][nt][k] = 0.0f;

        #pragma unroll
        for (int ks = 0; ks < 16; ks++) {
            const int d0 = ks * 8;
            uint32_t ah[2][4], al[2][4];
            #pragma unroll
            for (int mt = 0; mt < 2; mt++) {
                const float* qb = sQ + (wr + mt * 16 + lq) * QSTR + d0 + lr;
                split_tf32(qb[0],            ah[mt][0], al[mt][0]);
                split_tf32(qb[8 * QSTR],     ah[mt][1], al[mt][1]);
                split_tf32(qb[4],            ah[mt][2], al[mt][2]);
                split_tf32(qb[8 * QSTR + 4], ah[mt][3], al[mt][3]);
            }
            #pragma unroll
            for (int nt = 0; nt < 4; nt++) {
                const float* kb = sK + (wcS + nt * 8 + lq) * KSTR + d0 + lr;
                uint32_t bh0, bh1, bl0, bl1;
                split_tf32(kb[0], bh0, bl0);
                split_tf32(kb[4], bh1, bl1);
                #pragma unroll
                for (int mt = 0; mt < 2; mt++) {
                    mma8(S[mt][nt], al[mt][0], al[mt][1], al[mt][2], al[mt][3], bh0, bh1);
                    mma8(S[mt][nt], ah[mt][0], ah[mt][1], ah[mt][2], ah[mt][3], bl0, bl1);
                    mma8(S[mt][nt], ah[mt][0], ah[mt][1], ah[mt][2], ah[mt][3], bh0, bh1);
                }
            }
        }

        // ---- epilogue: threshold + causal + exp -> P smem, rowsum regs ----
        const bool diag = (kt >= 2 * qt);
        #pragma unroll
        for (int mt = 0; mt < 2; mt++) {
            const int rlo = wr + mt * 16 + lq;        // local row (c0,c1)
            const int rhi = rlo + 8;                  // local row (c2,c3)
            const int grlo = qt * TQ + rlo, grhi = qt * TQ + rhi;
            #pragma unroll
            for (int nt = 0; nt < 4; nt++) {
                const int c = wcS + nt * 8 + lr * 2;  // local col
                const int gc = kt * TK + c;
                float e0 = (S[mt][nt][0] > 0.3f) ? __expf(S[mt][nt][0] * ISD) : 1.0f;
                float e1 = (S[mt][nt][1] > 0.3f) ? __expf(S[mt][nt][1] * ISD) : 1.0f;
                float e2 = (S[mt][nt][2] > 0.3f) ? __expf(S[mt][nt][2] * ISD) : 1.0f;
                float e3 = (S[mt][nt][3] > 0.3f) ? __expf(S[mt][nt][3] * ISD) : 1.0f;
                if (diag) {
                    if (gc     > grlo) e0 = 0.0f;
                    if (gc + 1 > grlo) e1 = 0.0f;
                    if (gc     > grhi) e2 = 0.0f;
                    if (gc + 1 > grhi) e3 = 0.0f;
                }
                rs[mt][0] += e0 + e1;
                rs[mt][1] += e2 + e3;
                *(float2*)(sP + rlo * PSTR + c) = make_float2(e0, e1);
                *(float2*)(sP + rhi * PSTR + c) = make_float2(e2, e3);
            }
        }
        __syncthreads();   // P complete before PV reads

        // ---- PV: 3xTF32, warp tile 32 rows x 64 cols, k=64 ----
        #pragma unroll
        for (int ks = 0; ks < 8; ks++) {
            const int k0 = ks * 8;
            uint32_t ah[2][4], al[2][4];
            #pragma unroll
            for (int mt = 0; mt < 2; mt++) {
                const float* pb = sP + (wr + mt * 16 + lq) * PSTR + k0 + lr;
                split_tf32(pb[0],            ah[mt][0], al[mt][0]);
                split_tf32(pb[8 * PSTR],     ah[mt][1], al[mt][1]);
                split_tf32(pb[4],            ah[mt][2], al[mt][2]);
                split_tf32(pb[8 * PSTR + 4], ah[mt][3], al[mt][3]);
            }
            #pragma unroll
            for (int nt = 0; nt < 8; nt++) {
                const float* vb = sV + (k0 + lr) * VSTR + wcO + nt * 8 + lq;
                uint32_t bh0, bh1, bl0, bl1;
                split_tf32(vb[0],        bh0, bl0);
                split_tf32(vb[4 * VSTR], bh1, bl1);
                #pragma unroll
                for (int mt = 0; mt < 2; mt++) {
                    mma8(Oa[mt][nt], al[mt][0], al[mt][1], al[mt][2], al[mt][3], bh0, bh1);
                    mma8(Oa[mt][nt], ah[mt][0], ah[mt][1], ah[mt][2], ah[mt][3], bl0, bl1);
                    mma8(Oa[mt][nt], ah[mt][0], ah[mt][1], ah[mt][2], ah[mt][3], bh0, bh1);
                }
            }
        }
    }

    // ---- rowsum reduction: quad shfl, then combine the two col-half warps ----
    #pragma unroll
    for (int mt = 0; mt < 2; mt++)
        #pragma unroll
        for (int h = 0; h < 2; h++) {
            rs[mt][h] += __shfl_xor_sync(0xffffffffu, rs[mt][h], 1);
            rs[mt][h] += __shfl_xor_sync(0xffffffffu, rs[mt][h], 2);
        }
    __syncthreads();
    if (lr == 0) {
        const int half = warp >> 2;
        #pragma unroll
        for (int mt = 0; mt < 2; mt++) {
            sRS[half * TQ + wr + mt * 16 + lq]     = rs[mt][0];
            sRS[half * TQ + wr + mt * 16 + 8 + lq] = rs[mt][1];
        }
    }
    __syncthreads();

    // ---- normalize + store ----
    float* outb = Og + ((size_t)b * SLEN + (size_t)qt * TQ) * DDIM;
    #pragma unroll
    for (int mt = 0; mt < 2; mt++) {
        const int rlo = wr + mt * 16 + lq;
        const int rhi = rlo + 8;
        const float invlo = 1.0f / (sRS[rlo] + sRS[TQ + rlo]);
        const float invhi = 1.0f / (sRS[rhi] + sRS[TQ + rhi]);
        #pragma unroll
        for (int nt = 0; nt < 8; nt++) {
            const int c = wcO + nt * 8 + lr * 2;
            *(float2*)(outb + (size_t)rlo * DDIM + c) =
                make_float2(Oa[mt][nt][0] * invlo, Oa[mt][nt][1] * invlo);
            *(float2*)(outb + (size_t)rhi * DDIM + c) =
                make_float2(Oa[mt][nt][2] * invhi, Oa[mt][nt][3] * invhi);
        }
    }
}

extern "C" void kernel_launch(void* const* d_in, const int* in_sizes, int n_in,
                              void* d_out, int out_size) {
    (void)in_sizes; (void)n_in; (void)out_size;
    const float* Q = (const float*)d_in[0];
    const float* T = (const float*)d_in[1];
    const float* V = (const float*)d_in[2];
    float* O = (float*)d_out;

    cudaFuncSetAttribute(attn_mma, cudaFuncAttributeMaxDynamicSharedMemorySize, SMEM_BYTES);

    dim3 grid(SLEN / TQ, NB);
    attn_mma<<<grid, THREADS, SMEM_BYTES>>>(Q, T, V, O);
}

// round 5
// speedup vs baseline: 6.3051x; 5.9335x over previous
#include <cuda_runtime.h>
#include <cuda_fp16.h>
#include <cstdint>

#define SLEN 2048
#define DDIM 128
#define NB 16
#define TQ 128
#define TK 64
#define THREADS 256

// smem strides in halves (conflict-free: bank = 4*row + lane_in_quad)
#define QS 136
#define KS 136
#define VS 72
#define PS 72

// smem offsets in halves
#define SQ_H 0
#define SK0_H 17408
#define SK1_H 26112
#define SV0_H 34816
#define SV1_H 44032
#define SP_H 53248
#define SRS_B 124928                 // byte offset of 256-float rowsum array
#define SMEM_BYTES (124928 + 1024)

static __device__ __half g_Qh[(size_t)NB * SLEN * DDIM];
static __device__ __half g_Th[(size_t)NB * SLEN * DDIM];
static __device__ __half g_Vt[(size_t)NB * DDIM * SLEN];   // transposed V

__device__ __forceinline__ uint32_t smem_u32(const void* p) {
    uint32_t a;
    asm("{ .reg .u64 t; cvta.to.shared.u64 t, %1; cvt.u32.u64 %0, t; }" : "=r"(a) : "l"(p));
    return a;
}
__device__ __forceinline__ void cp16(uint32_t dst, const void* src) {
    asm volatile("cp.async.cg.shared.global [%0], [%1], 16;" :: "r"(dst), "l"(src) : "memory");
}
#define CP_COMMIT() asm volatile("cp.async.commit_group;" ::: "memory")
#define CP_WAIT1()  asm volatile("cp.async.wait_group 1;" ::: "memory")

__device__ __forceinline__ void mma16(float* d, uint32_t a0, uint32_t a1, uint32_t a2,
                                      uint32_t a3, uint32_t b0, uint32_t b1) {
    asm volatile("mma.sync.aligned.m16n8k16.row.col.f32.f16.f16.f32 "
                 "{%0,%1,%2,%3}, {%4,%5,%6,%7}, {%8,%9}, {%0,%1,%2,%3};"
                 : "+f"(d[0]), "+f"(d[1]), "+f"(d[2]), "+f"(d[3])
                 : "r"(a0), "r"(a1), "r"(a2), "r"(a3), "r"(b0), "r"(b1));
}
__device__ __forceinline__ uint32_t lds32(const __half* p) {
    return *(const uint32_t*)p;
}

// ---------------- conversion pre-kernels ----------------
__global__ void convF2H(const float* __restrict__ src, __half* __restrict__ dst) {
    int i = blockIdx.x * blockDim.x + threadIdx.x;   // i < n/4
    float4 v = ((const float4*)src)[i];
    __half2* d2 = (__half2*)dst;
    d2[2 * i + 0] = __floats2half2_rn(v.x, v.y);
    d2[2 * i + 1] = __floats2half2_rn(v.z, v.w);
}

__global__ void vTh_kernel(const float* __restrict__ V, __half* __restrict__ Vt) {
    __shared__ float t[32][33];
    const int b = blockIdx.z;
    const int k0 = blockIdx.x * 32, d0 = blockIdx.y * 32;
    const int tx = threadIdx.x & 31, ty = threadIdx.x >> 5;  // 32x8
    const float* vb = V + (size_t)b * SLEN * DDIM;
    __half* vtb = Vt + (size_t)b * DDIM * SLEN;
    #pragma unroll
    for (int i = 0; i < 32; i += 8)
        t[ty + i][tx] = vb[(size_t)(k0 + ty + i) * DDIM + d0 + tx];
    __syncthreads();
    #pragma unroll
    for (int i = 0; i < 32; i += 8)
        vtb[(size_t)(d0 + ty + i) * SLEN + k0 + tx] = __float2half_rn(t[tx][ty + i]);
}

// ---------------- main attention kernel ----------------
__global__ __launch_bounds__(THREADS, 1)
void attn_h(const __half* __restrict__ Qh, const __half* __restrict__ Th,
            const __half* __restrict__ Vt, float* __restrict__ Og) {
    extern __shared__ __align__(16) char smraw[];
    __half* sh = (__half*)smraw;
    float* sRS = (float*)(smraw + SRS_B);
    const uint32_t sb = smem_u32(smraw);

    // globally descending work order (LPT)
    const int idx = blockIdx.x;
    const int qt = (SLEN / TQ - 1) - idx / NB;
    const int b = idx % NB;

    const int tid = threadIdx.x;
    const int warp = tid >> 5, lane = tid & 31;
    const int lq = lane >> 2;            // group row 0..7
    const int lr = lane & 3;             // lane in quad
    const int wr = (warp & 3) * 32;      // warp q-row base
    const int wcS = (warp >> 2) * 32;    // QK col base
    const int wcO = (warp >> 2) * 64;    // PV col base
    const float ISD = 0.08838834764831845f;

    const __half* qg = Qh + ((size_t)b * SLEN + (size_t)qt * TQ) * DDIM;
    const int nkt = 2 * qt + 2;

    // ---- prologue: Q + K0 + V0 via cp.async (group 0) ----
    #pragma unroll
    for (int it = 0; it < 8; it++) {           // Q: 128 rows x 16 chunks
        int i = it * THREADS + tid;
        int r = i >> 4, c = i & 15;
        cp16(sb + (SQ_H + r * QS + c * 8) * 2, qg + (size_t)r * DDIM + c * 8);
    }
    {
        const __half* kg = Th + ((size_t)b * SLEN) * DDIM;           // kt=0
        const __half* vg = Vt + (size_t)b * DDIM * SLEN;             // kt=0
        #pragma unroll
        for (int it = 0; it < 4; it++) {       // K: 64 rows x 16 chunks
            int i = it * THREADS + tid;
            int r = i >> 4, c = i & 15;
            cp16(sb + (SK0_H + r * KS + c * 8) * 2, kg + (size_t)r * DDIM + c * 8);
        }
        #pragma unroll
        for (int it = 0; it < 4; it++) {       // V: 128 rows x 8 chunks
            int i = it * THREADS + tid;
            int r = i >> 3, c = i & 7;
            cp16(sb + (SV0_H + r * VS + c * 8) * 2, vg + (size_t)r * SLEN + c * 8);
        }
    }
    CP_COMMIT();

    float Oa[2][8][4];
    #pragma unroll
    for (int mt = 0; mt < 2; mt++)
        #pragma unroll
        for (int nt = 0; nt < 8; nt++)
            #pragma unroll
            for (int k = 0; k < 4; k++) Oa[mt][nt][k] = 0.0f;
    float rs[2][2] = {{0.0f, 0.0f}, {0.0f, 0.0f}};

    for (int kt = 0; kt < nkt; kt++) {
        // ---- prefetch tile kt+1 into alternate buffers ----
        if (kt + 1 < nkt) {
            const int nb_ = (kt + 1) & 1;
            const uint32_t skb = sb + (nb_ ? SK1_H : SK0_H) * 2;
            const uint32_t svb = sb + (nb_ ? SV1_H : SV0_H) * 2;
            const __half* kg = Th + ((size_t)b * SLEN + (size_t)(kt + 1) * TK) * DDIM;
            const __half* vg = Vt + (size_t)b * DDIM * SLEN + (size_t)(kt + 1) * TK;
            #pragma unroll
            for (int it = 0; it < 4; it++) {
                int i = it * THREADS + tid;
                int r = i >> 4, c = i & 15;
                cp16(skb + (r * KS + c * 8) * 2, kg + (size_t)r * DDIM + c * 8);
            }
            #pragma unroll
            for (int it = 0; it < 4; it++) {
                int i = it * THREADS + tid;
                int r = i >> 3, c = i & 7;
                cp16(svb + (r * VS + c * 8) * 2, vg + (size_t)r * SLEN + c * 8);
            }
        }
        CP_COMMIT();
        CP_WAIT1();               // current tile's data resident
        __syncthreads();

        const __half* sK = sh + ((kt & 1) ? SK1_H : SK0_H);
        const __half* sV = sh + ((kt & 1) ? SV1_H : SV0_H);
        const __half* sQ = sh + SQ_H;
        __half* sP = sh + SP_H;

        // ---- QK^T: fp16 m16n8k16, warp tile 32x32 ----
        float S[2][4][4];
        #pragma unroll
        for (int mt = 0; mt < 2; mt++)
            #pragma unroll
            for (int nt = 0; nt < 4; nt++)
                #pragma unroll
                for (int k = 0; k < 4; k++) S[mt][nt][k] = 0.0f;

        #pragma unroll
        for (int ks = 0; ks < 8; ks++) {
            const int k0 = ks * 16;
            uint32_t a[2][4];
            #pragma unroll
            for (int mt = 0; mt < 2; mt++) {
                const __half* qb = sQ + (wr + mt * 16 + lq) * QS + k0 + 2 * lr;
                a[mt][0] = lds32(qb);
                a[mt][1] = lds32(qb + 8 * QS);
                a[mt][2] = lds32(qb + 8);
                a[mt][3] = lds32(qb + 8 * QS + 8);
            }
            #pragma unroll
            for (int nt = 0; nt < 4; nt++) {
                const __half* kb = sK + (wcS + nt * 8 + lq) * KS + k0 + 2 * lr;
                uint32_t b0 = lds32(kb);
                uint32_t b1 = lds32(kb + 8);
                #pragma unroll
                for (int mt = 0; mt < 2; mt++)
                    mma16(S[mt][nt], a[mt][0], a[mt][1], a[mt][2], a[mt][3], b0, b1);
            }
        }

        // ---- epilogue: threshold + causal + exp -> fp16 P, fp32 rowsum ----
        const bool diag = (kt >= 2 * qt);
        #pragma unroll
        for (int mt = 0; mt < 2; mt++) {
            const int rlo = wr + mt * 16 + lq;
            const int rhi = rlo + 8;
            const int grlo = qt * TQ + rlo, grhi = qt * TQ + rhi;
            #pragma unroll
            for (int nt = 0; nt < 4; nt++) {
                const int c = wcS + nt * 8 + lr * 2;
                const int gc = kt * TK + c;
                float e0 = (S[mt][nt][0] > 0.3f) ? __expf(S[mt][nt][0] * ISD) : 1.0f;
                float e1 = (S[mt][nt][1] > 0.3f) ? __expf(S[mt][nt][1] * ISD) : 1.0f;
                float e2 = (S[mt][nt][2] > 0.3f) ? __expf(S[mt][nt][2] * ISD) : 1.0f;
                float e3 = (S[mt][nt][3] > 0.3f) ? __expf(S[mt][nt][3] * ISD) : 1.0f;
                if (diag) {
                    if (gc     > grlo) e0 = 0.0f;
                    if (gc + 1 > grlo) e1 = 0.0f;
                    if (gc     > grhi) e2 = 0.0f;
                    if (gc + 1 > grhi) e3 = 0.0f;
                }
                rs[mt][0] += e0 + e1;
                rs[mt][1] += e2 + e3;
                *(__half2*)(sP + rlo * PS + c) = __floats2half2_rn(e0, e1);
                *(__half2*)(sP + rhi * PS + c) = __floats2half2_rn(e2, e3);
            }
        }
        __syncthreads();   // full P tile visible

        // ---- PV: fp16 m16n8k16, warp tile 32x64, k=64 ----
        #pragma unroll
        for (int ks = 0; ks < 4; ks++) {
            const int k0 = ks * 16;
            uint32_t a[2][4];
            #pragma unroll
            for (int mt = 0; mt < 2; mt++) {
                const __half* pb = sP + (wr + mt * 16 + lq) * PS + k0 + 2 * lr;
                a[mt][0] = lds32(pb);
                a[mt][1] = lds32(pb + 8 * PS);
                a[mt][2] = lds32(pb + 8);
                a[mt][3] = lds32(pb + 8 * PS + 8);
            }
            #pragma unroll
            for (int nt = 0; nt < 8; nt++) {
                const __half* vb = sV + (wcO + nt * 8 + lq) * VS + k0 + 2 * lr;
                uint32_t b0 = lds32(vb);
                uint32_t b1 = lds32(vb + 8);
                #pragma unroll
                for (int mt = 0; mt < 2; mt++)
                    mma16(Oa[mt][nt], a[mt][0], a[mt][1], a[mt][2], a[mt][3], b0, b1);
            }
        }
        __syncthreads();   // tile fully consumed; buffers reusable
    }

    // ---- rowsum reduction across quads, then across col-half warps ----
    #pragma unroll
    for (int mt = 0; mt < 2; mt++)
        #pragma unroll
        for (int h = 0; h < 2; h++) {
            rs[mt][h] += __shfl_xor_sync(0xffffffffu, rs[mt][h], 1);
            rs[mt][h] += __shfl_xor_sync(0xffffffffu, rs[mt][h], 2);
        }
    if (lr == 0) {
        const int half_ = warp >> 2;
        #pragma unroll
        for (int mt = 0; mt < 2; mt++) {
            sRS[half_ * TQ + wr + mt * 16 + lq]     = rs[mt][0];
            sRS[half_ * TQ + wr + mt * 16 + 8 + lq] = rs[mt][1];
        }
    }
    __syncthreads();

    // ---- normalize + store ----
    float* outb = Og + ((size_t)b * SLEN + (size_t)qt * TQ) * DDIM;
    #pragma unroll
    for (int mt = 0; mt < 2; mt++) {
        const int rlo = wr + mt * 16 + lq;
        const int rhi = rlo + 8;
        const float invlo = 1.0f / (sRS[rlo] + sRS[TQ + rlo]);
        const float invhi = 1.0f / (sRS[rhi] + sRS[TQ + rhi]);
        #pragma unroll
        for (int nt = 0; nt < 8; nt++) {
            const int c = wcO + nt * 8 + lr * 2;
            *(float2*)(outb + (size_t)rlo * DDIM + c) =
                make_float2(Oa[mt][nt][0] * invlo, Oa[mt][nt][1] * invlo);
            *(float2*)(outb + (size_t)rhi * DDIM + c) =
                make_float2(Oa[mt][nt][2] * invhi, Oa[mt][nt][3] * invhi);
        }
    }
}

extern "C" void kernel_launch(void* const* d_in, const int* in_sizes, int n_in,
                              void* d_out, int out_size) {
    (void)in_sizes; (void)n_in; (void)out_size;
    const float* Q = (const float*)d_in[0];
    const float* T = (const float*)d_in[1];
    const float* V = (const float*)d_in[2];
    float* O = (float*)d_out;

    __half *qh, *th, *vt;
    cudaGetSymbolAddress((void**)&qh, g_Qh);
    cudaGetSymbolAddress((void**)&th, g_Th);
    cudaGetSymbolAddress((void**)&vt, g_Vt);

    const int n4 = NB * SLEN * DDIM / 4;
    convF2H<<<n4 / 256, 256>>>(Q, qh);
    convF2H<<<n4 / 256, 256>>>(T, th);
    dim3 tgrid(SLEN / 32, DDIM / 32, NB);
    vTh_kernel<<<tgrid, 256>>>(V, vt);

    cudaFuncSetAttribute(attn_h, cudaFuncAttributeMaxDynamicSharedMemorySize, SMEM_BYTES);
    attn_h<<<(SLEN / TQ) * NB, THREADS, SMEM_BYTES>>>(qh, th, vt, O);
}

// round 7
// speedup vs baseline: 6.8990x; 1.0942x over previous
#include <cuda_runtime.h>
#include <cuda_fp16.h>
#include <cstdint>

#define SLEN 2048
#define DDIM 128
#define NB 16
#define TQ 128
#define TK 64
#define THREADS 256

// strides in halves
#define QS 136
#define KS 136
#define VS 72
#define PS 72

// smem offsets in halves
#define SQ_H 0
#define SK0_H 17408
#define SK1_H 26112
#define SV0_H 34816
#define SV1_H 44032
#define SP0_H 53248
#define SP1_H 62464
#define SRS_B 143360
#define SMEM_BYTES 145408

static __device__ __half g_Qh[(size_t)NB * SLEN * DDIM];
static __device__ __half g_Th[(size_t)NB * SLEN * DDIM];
static __device__ __half g_Vt[(size_t)NB * DDIM * SLEN];

__device__ __forceinline__ uint32_t smem_u32(const void* p) {
    uint32_t a;
    asm("{ .reg .u64 t; cvta.to.shared.u64 t, %1; cvt.u32.u64 %0, t; }" : "=r"(a) : "l"(p));
    return a;
}
__device__ __forceinline__ void cp16(uint32_t dst, const void* src) {
    asm volatile("cp.async.cg.shared.global [%0], [%1], 16;" :: "r"(dst), "l"(src) : "memory");
}
#define CP_COMMIT() asm volatile("cp.async.commit_group;" ::: "memory")
#define CP_WAIT0()  asm volatile("cp.async.wait_group 0;" ::: "memory")

__device__ __forceinline__ void ldsm4(uint32_t& r0, uint32_t& r1, uint32_t& r2, uint32_t& r3,
                                      uint32_t a) {
    asm volatile("ldmatrix.sync.aligned.m8n8.x4.shared.b16 {%0,%1,%2,%3}, [%4];"
                 : "=r"(r0), "=r"(r1), "=r"(r2), "=r"(r3) : "r"(a));
}
__device__ __forceinline__ void mma16(float* d, uint32_t a0, uint32_t a1, uint32_t a2,
                                      uint32_t a3, uint32_t b0, uint32_t b1) {
    asm volatile("mma.sync.aligned.m16n8k16.row.col.f32.f16.f16.f32 "
                 "{%0,%1,%2,%3}, {%4,%5,%6,%7}, {%8,%9}, {%0,%1,%2,%3};"
                 : "+f"(d[0]), "+f"(d[1]), "+f"(d[2]), "+f"(d[3])
                 : "r"(a0), "r"(a1), "r"(a2), "r"(a3), "r"(b0), "r"(b1));
}
__device__ __forceinline__ uint32_t ex2h2(uint32_t u) {
    uint32_t r;
    asm("ex2.approx.f16x2 %0, %1;" : "=r"(r) : "r"(u));
    return r;
}

// ---------------- pre-kernels ----------------
__global__ void convQT(const float* __restrict__ Q, const float* __restrict__ T,
                       __half* __restrict__ Qh, __half* __restrict__ Th) {
    const float* src = blockIdx.y ? T : Q;
    __half2* dst = (__half2*)(blockIdx.y ? Th : Qh);
    int i = blockIdx.x * blockDim.x + threadIdx.x;
    float4 v = ((const float4*)src)[i];
    dst[2 * i + 0] = __floats2half2_rn(v.x, v.y);
    dst[2 * i + 1] = __floats2half2_rn(v.z, v.w);
}

__global__ void vTh_kernel(const float* __restrict__ V, __half* __restrict__ Vt) {
    __shared__ float t[64][65];
    const int b = blockIdx.z;
    const int k0 = blockIdx.x * 64, d0 = blockIdx.y * 64;
    const int tid = threadIdx.x;
    const float* vb = V + (size_t)b * SLEN * DDIM;
    #pragma unroll
    for (int it = 0; it < 4; it++) {
        int i = it * 256 + tid;
        int r = i >> 4, c = i & 15;
        float4 v = *(const float4*)(vb + (size_t)(k0 + r) * DDIM + d0 + c * 4);
        t[r][c * 4 + 0] = v.x;    // scalar stores: row stride 65 is not 16B-aligned
        t[r][c * 4 + 1] = v.y;
        t[r][c * 4 + 2] = v.z;
        t[r][c * 4 + 3] = v.w;
    }
    __syncthreads();
    __half* out = Vt + (size_t)b * DDIM * SLEN;
    #pragma unroll
    for (int it = 0; it < 8; it++) {
        int i = it * 256 + tid;
        int r = i >> 5, p = i & 31;
        *(__half2*)(out + (size_t)(d0 + r) * SLEN + k0 + 2 * p) =
            __floats2half2_rn(t[2 * p][r], t[2 * p + 1][r]);
    }
}

// ---------------- main attention kernel ----------------
__global__ __launch_bounds__(THREADS, 1)
void attn_h(const __half* __restrict__ Qh, const __half* __restrict__ Th,
            const __half* __restrict__ Vt, float* __restrict__ Og) {
    extern __shared__ __align__(16) char smraw[];
    __half* sh = (__half*)smraw;
    float* sRS = (float*)(smraw + SRS_B);
    const uint32_t sb = smem_u32(smraw);

    const int idx = blockIdx.x;
    const int qt = (SLEN / TQ - 1) - idx / NB;   // LPT: heavy first
    const int b = idx % NB;

    const int tid = threadIdx.x;
    const int warp = tid >> 5, lane = tid & 31;
    const int lq = lane >> 2;
    const int lr = lane & 3;
    const int wr = (warp & 3) * 32;
    const int wcS = (warp >> 2) * 32;
    const int wcO = (warp >> 2) * 64;
    const float CEX = 0.12751754f;   // log2(e)/sqrt(128)
    const float BIGN = -30000.0f;

    const __half* qg = Qh + ((size_t)b * SLEN + (size_t)qt * TQ) * DDIM;
    const int nkt = 2 * qt + 2;

    // ldmatrix lane base addresses (bytes)
    const int l15 = lane & 15;
    const int lc8 = (lane >> 4) << 3;            // +8 halves for hi half-warp
    uint32_t qa[2], kb0[2][2], vb0[2][4], pa0[2][2];
    #pragma unroll
    for (int mt = 0; mt < 2; mt++)
        qa[mt] = sb + 2 * (SQ_H + (wr + mt * 16 + l15) * QS + lc8);
    #pragma unroll
    for (int bf = 0; bf < 2; bf++) {
        const int kh = bf ? SK1_H : SK0_H;
        const int vh = bf ? SV1_H : SV0_H;
        const int ph = bf ? SP1_H : SP0_H;
        #pragma unroll
        for (int p = 0; p < 2; p++)
            kb0[bf][p] = sb + 2 * (kh + (wcS + p * 16 + l15) * KS + lc8);
        #pragma unroll
        for (int p = 0; p < 4; p++)
            vb0[bf][p] = sb + 2 * (vh + (wcO + p * 16 + l15) * VS + lc8);
        #pragma unroll
        for (int mt = 0; mt < 2; mt++)
            pa0[bf][mt] = sb + 2 * (ph + (wr + mt * 16 + l15) * PS + lc8);
    }

    // ---- prologue: Q + K0 + V0 ----
    #pragma unroll
    for (int it = 0; it < 8; it++) {
        int i = it * THREADS + tid;
        int r = i >> 4, c = i & 15;
        cp16(sb + 2 * (SQ_H + r * QS + c * 8), qg + (size_t)r * DDIM + c * 8);
    }
    {
        const __half* kg = Th + (size_t)b * SLEN * DDIM;
        const __half* vg = Vt + (size_t)b * DDIM * SLEN;
        #pragma unroll
        for (int it = 0; it < 4; it++) {
            int i = it * THREADS + tid;
            int r = i >> 4, c = i & 15;
            cp16(sb + 2 * (SK0_H + r * KS + c * 8), kg + (size_t)r * DDIM + c * 8);
        }
        #pragma unroll
        for (int it = 0; it < 4; it++) {
            int i = it * THREADS + tid;
            int r = i >> 3, c = i & 7;
            cp16(sb + 2 * (SV0_H + r * VS + c * 8), vg + (size_t)r * SLEN + c * 8);
        }
    }
    CP_COMMIT();

    float Oa[2][8][4];
    #pragma unroll
    for (int mt = 0; mt < 2; mt++)
        #pragma unroll
        for (int nt = 0; nt < 8; nt++)
            #pragma unroll
            for (int k = 0; k < 4; k++) Oa[mt][nt][k] = 0.0f;
    float rs[2][2] = {{0.0f, 0.0f}, {0.0f, 0.0f}};

    for (int kt = 0; kt < nkt; kt++) {
        const int bf = kt & 1;
        CP_WAIT0();
        __syncthreads();    // K/V(kt) published; PV(kt-1) complete

        // ---- prefetch kt+1 ----
        if (kt + 1 < nkt) {
            const int nb_ = bf ^ 1;
            const uint32_t skb = sb + 2 * (nb_ ? SK1_H : SK0_H);
            const uint32_t svb = sb + 2 * (nb_ ? SV1_H : SV0_H);
            const __half* kg = Th + ((size_t)b * SLEN + (size_t)(kt + 1) * TK) * DDIM;
            const __half* vg = Vt + (size_t)b * DDIM * SLEN + (size_t)(kt + 1) * TK;
            #pragma unroll
            for (int it = 0; it < 4; it++) {
                int i = it * THREADS + tid;
                int r = i >> 4, c = i & 15;
                cp16(skb + 2 * (r * KS + c * 8), kg + (size_t)r * DDIM + c * 8);
            }
            #pragma unroll
            for (int it = 0; it < 4; it++) {
                int i = it * THREADS + tid;
                int r = i >> 3, c = i & 7;
                cp16(svb + 2 * (r * VS + c * 8), vg + (size_t)r * SLEN + c * 8);
            }
        }
        CP_COMMIT();

        // ---- QK^T (fp16 m16n8k16, warp 32x32) ----
        float S[2][4][4];
        #pragma unroll
        for (int mt = 0; mt < 2; mt++)
            #pragma unroll
            for (int nt = 0; nt < 4; nt++)
                #pragma unroll
                for (int k = 0; k < 4; k++) S[mt][nt][k] = 0.0f;

        #pragma unroll
        for (int ks = 0; ks < 8; ks++) {
            const uint32_t ko = 32u * ks;   // +16 halves per ks
            uint32_t a[2][4];
            ldsm4(a[0][0], a[0][1], a[0][2], a[0][3], qa[0] + ko);
            ldsm4(a[1][0], a[1][1], a[1][2], a[1][3], qa[1] + ko);
            #pragma unroll
            for (int p = 0; p < 2; p++) {
                uint32_t r0, r1, r2, r3;
                ldsm4(r0, r1, r2, r3, kb0[bf][p] + ko);
                #pragma unroll
                for (int mt = 0; mt < 2; mt++) {
                    mma16(S[mt][2 * p + 0], a[mt][0], a[mt][1], a[mt][2], a[mt][3], r0, r2);
                    mma16(S[mt][2 * p + 1], a[mt][0], a[mt][1], a[mt][2], a[mt][3], r1, r3);
                }
            }
        }

        // ---- epilogue: threshold + causal + f16x2 exp2 -> P[bf] ----
        const bool diag = (kt >= 2 * qt);
        __half* sP = sh + (bf ? SP1_H : SP0_H);
        #pragma unroll
        for (int mt = 0; mt < 2; mt++) {
            const int rlo = wr + mt * 16 + lq;
            const int rhi = rlo + 8;
            const int grlo = qt * TQ + rlo, grhi = qt * TQ + rhi;
            __half2 accLo = __float2half2_rn(0.0f);
            __half2 accHi = __float2half2_rn(0.0f);
            #pragma unroll
            for (int nt = 0; nt < 4; nt++) {
                const int c = wcS + nt * 8 + lr * 2;
                const int gc = kt * TK + c;
                float l0 = (S[mt][nt][0] > 0.3f) ? S[mt][nt][0] * CEX : 0.0f;
                float l1 = (S[mt][nt][1] > 0.3f) ? S[mt][nt][1] * CEX : 0.0f;
                float l2 = (S[mt][nt][2] > 0.3f) ? S[mt][nt][2] * CEX : 0.0f;
                float l3 = (S[mt][nt][3] > 0.3f) ? S[mt][nt][3] * CEX : 0.0f;
                if (diag) {
                    if (gc     > grlo) l0 = BIGN;
                    if (gc + 1 > grlo) l1 = BIGN;
                    if (gc     > grhi) l2 = BIGN;
                    if (gc + 1 > grhi) l3 = BIGN;
                }
                __half2 hlo = __floats2half2_rn(l0, l1);
                __half2 hhi = __floats2half2_rn(l2, l3);
                uint32_t ulo = ex2h2(*(uint32_t*)&hlo);
                uint32_t uhi = ex2h2(*(uint32_t*)&hhi);
                __half2 plo = *(__half2*)&ulo;
                __half2 phi = *(__half2*)&uhi;
                *(__half2*)(sP + rlo * PS + c) = plo;
                *(__half2*)(sP + rhi * PS + c) = phi;
                accLo = __hadd2(accLo, plo);
                accHi = __hadd2(accHi, phi);
            }
            float2 fl = __half22float2(accLo);
            float2 fh = __half22float2(accHi);
            rs[mt][0] += fl.x + fl.y;
            rs[mt][1] += fh.x + fh.y;
        }
        __syncthreads();   // P[bf] published

        // ---- PV (fp16 m16n8k16, warp 32x64) ----
        #pragma unroll
        for (int ks = 0; ks < 4; ks++) {
            const uint32_t ko = 32u * ks;
            uint32_t a[2][4];
            ldsm4(a[0][0], a[0][1], a[0][2], a[0][3], pa0[bf][0] + ko);
            ldsm4(a[1][0], a[1][1], a[1][2], a[1][3], pa0[bf][1] + ko);
            #pragma unroll
            for (int p = 0; p < 4; p++) {
                uint32_t r0, r1, r2, r3;
                ldsm4(r0, r1, r2, r3, vb0[bf][p] + ko);
                #pragma unroll
                for (int mt = 0; mt < 2; mt++) {
                    mma16(Oa[mt][2 * p + 0], a[mt][0], a[mt][1], a[mt][2], a[mt][3], r0, r2);
                    mma16(Oa[mt][2 * p + 1], a[mt][0], a[mt][1], a[mt][2], a[mt][3], r1, r3);
                }
            }
        }
    }

    // ---- rowsum reduction ----
    #pragma unroll
    for (int mt = 0; mt < 2; mt++)
        #pragma unroll
        for (int h = 0; h < 2; h++) {
            rs[mt][h] += __shfl_xor_sync(0xffffffffu, rs[mt][h], 1);
            rs[mt][h] += __shfl_xor_sync(0xffffffffu, rs[mt][h], 2);
        }
    __syncthreads();
    if (lr == 0) {
        const int half_ = warp >> 2;
        #pragma unroll
        for (int mt = 0; mt < 2; mt++) {
            sRS[half_ * TQ + wr + mt * 16 + lq]     = rs[mt][0];
            sRS[half_ * TQ + wr + mt * 16 + 8 + lq] = rs[mt][1];
        }
    }
    __syncthreads();

    // ---- normalize + store ----
    float* outb = Og + ((size_t)b * SLEN + (size_t)qt * TQ) * DDIM;
    #pragma unroll
    for (int mt = 0; mt < 2; mt++) {
        const int rlo = wr + mt * 16 + lq;
        const int rhi = rlo + 8;
        const float invlo = 1.0f / (sRS[rlo] + sRS[TQ + rlo]);
        const float invhi = 1.0f / (sRS[rhi] + sRS[TQ + rhi]);
        #pragma unroll
        for (int nt = 0; nt < 8; nt++) {
            const int c = wcO + nt * 8 + lr * 2;
            *(float2*)(outb + (size_t)rlo * DDIM + c) =
                make_float2(Oa[mt][nt][0] * invlo, Oa[mt][nt][1] * invlo);
            *(float2*)(outb + (size_t)rhi * DDIM + c) =
                make_float2(Oa[mt][nt][2] * invhi, Oa[mt][nt][3] * invhi);
        }
    }
}

extern "C" void kernel_launch(void* const* d_in, const int* in_sizes, int n_in,
                              void* d_out, int out_size) {
    (void)in_sizes; (void)n_in; (void)out_size;
    const float* Q = (const float*)d_in[0];
    const float* T = (const float*)d_in[1];
    const float* V = (const float*)d_in[2];
    float* O = (float*)d_out;

    __half *qh, *th, *vt;
    cudaGetSymbolAddress((void**)&qh, g_Qh);
    cudaGetSymbolAddress((void**)&th, g_Th);
    cudaGetSymbolAddress((void**)&vt, g_Vt);

    const int n4 = NB * SLEN * DDIM / 4;
    dim3 cgrid(n4 / 256, 2);
    convQT<<<cgrid, 256>>>(Q, T, qh, th);
    dim3 tgrid(SLEN / 64, DDIM / 64, NB);
    vTh_kernel<<<tgrid, 256>>>(V, vt);

    cudaFuncSetAttribute(attn_h, cudaFuncAttributeMaxDynamicSharedMemorySize, SMEM_BYTES);
    attn_h<<<(SLEN / TQ) * NB, THREADS, SMEM_BYTES>>>(qh, th, vt, O);
}

// round 8
// speedup vs baseline: 7.6579x; 1.1100x over previous
#include <cuda_runtime.h>
#include <cuda_fp16.h>
#include <cstdint>

#define SLEN 2048
#define DDIM 128
#define NB 16
#define TQ 64
#define TK 64
#define THREADS 128

// strides in halves
#define QS 136
#define KS 136
#define VS 136

// smem offsets in halves (each tile buffer = 64 rows x 136 = 8704 halves)
#define SQ_H 0
#define SK0_H 8704
#define SK1_H 17408
#define SV0_H 26112
#define SV1_H 34816
#define SMEM_BYTES (43520 * 2)     // 87040 B

static __device__ __half g_Qh[(size_t)NB * SLEN * DDIM];
static __device__ __half g_Th[(size_t)NB * SLEN * DDIM];
static __device__ __half g_Vh[(size_t)NB * SLEN * DDIM];

__device__ __forceinline__ uint32_t smem_u32(const void* p) {
    uint32_t a;
    asm("{ .reg .u64 t; cvta.to.shared.u64 t, %1; cvt.u32.u64 %0, t; }" : "=r"(a) : "l"(p));
    return a;
}
__device__ __forceinline__ void cp16(uint32_t dst, const void* src) {
    asm volatile("cp.async.cg.shared.global [%0], [%1], 16;" :: "r"(dst), "l"(src) : "memory");
}
#define CP_COMMIT() asm volatile("cp.async.commit_group;" ::: "memory")
#define CP_WAIT0()  asm volatile("cp.async.wait_group 0;" ::: "memory")

__device__ __forceinline__ void ldsm4(uint32_t& r0, uint32_t& r1, uint32_t& r2, uint32_t& r3,
                                      uint32_t a) {
    asm volatile("ldmatrix.sync.aligned.m8n8.x4.shared.b16 {%0,%1,%2,%3}, [%4];"
                 : "=r"(r0), "=r"(r1), "=r"(r2), "=r"(r3) : "r"(a));
}
__device__ __forceinline__ void ldsm4t(uint32_t& r0, uint32_t& r1, uint32_t& r2, uint32_t& r3,
                                       uint32_t a) {
    asm volatile("ldmatrix.sync.aligned.m8n8.x4.trans.shared.b16 {%0,%1,%2,%3}, [%4];"
                 : "=r"(r0), "=r"(r1), "=r"(r2), "=r"(r3) : "r"(a));
}
__device__ __forceinline__ void mma16(float* d, uint32_t a0, uint32_t a1, uint32_t a2,
                                      uint32_t a3, uint32_t b0, uint32_t b1) {
    asm volatile("mma.sync.aligned.m16n8k16.row.col.f32.f16.f16.f32 "
                 "{%0,%1,%2,%3}, {%4,%5,%6,%7}, {%8,%9}, {%0,%1,%2,%3};"
                 : "+f"(d[0]), "+f"(d[1]), "+f"(d[2]), "+f"(d[3])
                 : "r"(a0), "r"(a1), "r"(a2), "r"(a3), "r"(b0), "r"(b1));
}
__device__ __forceinline__ uint32_t ex2h2(uint32_t u) {
    uint32_t r;
    asm("ex2.approx.f16x2 %0, %1;" : "=r"(r) : "r"(u));
    return r;
}

// ---------------- fused conversion pre-kernel (Q, T, V -> fp16) ----------------
__global__ void convAll(const float* __restrict__ Q, const float* __restrict__ T,
                        const float* __restrict__ V,
                        __half* __restrict__ Qh, __half* __restrict__ Th,
                        __half* __restrict__ Vh) {
    const float* s;
    __half* d;
    if (blockIdx.y == 0)      { s = Q; d = Qh; }
    else if (blockIdx.y == 1) { s = T; d = Th; }
    else                      { s = V; d = Vh; }
    int i = blockIdx.x * blockDim.x + threadIdx.x;
    float4 v = ((const float4*)s)[i];
    __half2 h0 = __floats2half2_rn(v.x, v.y);
    __half2 h1 = __floats2half2_rn(v.z, v.w);
    uint2 o = make_uint2(*(uint32_t*)&h0, *(uint32_t*)&h1);
    ((uint2*)d)[i] = o;
}

// ---------------- main attention kernel ----------------
__global__ __launch_bounds__(THREADS, 2)
void attn_h(const __half* __restrict__ Qh, const __half* __restrict__ Th,
            const __half* __restrict__ Vh, float* __restrict__ Og) {
    extern __shared__ __align__(16) char smraw[];
    const uint32_t sb = smem_u32(smraw);

    const int idx = blockIdx.x;
    const int qt = (SLEN / TQ - 1) - (idx >> 4);   // LPT: heavy first
    const int b = idx & 15;

    const int tid = threadIdx.x;
    const int warp = tid >> 5, lane = tid & 31;
    const int lq = lane >> 2;
    const int lr = lane & 3;
    const int wr = warp * 16;                     // warp q-row base (16 rows per warp)
    const float CEX = 0.12751754f;                // log2(e)/sqrt(128)
    const float BIGN = -30000.0f;

    const int l15 = lane & 15;
    const int lc8 = (lane >> 4) << 3;             // +8 halves for upper half-warp

    // ldmatrix base addresses (bytes)
    const uint32_t qa = sb + 2 * (SQ_H + (wr + l15) * QS + lc8);
    uint32_t kb[2][4], vb[2];
    #pragma unroll
    for (int bf = 0; bf < 2; bf++) {
        const int kh = bf ? SK1_H : SK0_H;
        const int vh = bf ? SV1_H : SV0_H;
        #pragma unroll
        for (int p = 0; p < 4; p++)
            kb[bf][p] = sb + 2 * (kh + (p * 16 + l15) * KS + lc8);
        vb[bf] = sb + 2 * (vh + l15 * VS + lc8);  // + p*32B (n) + ks*4352B (k rows)
    }

    const __half* qg = Qh + ((size_t)b * SLEN + (size_t)qt * TQ) * DDIM;

    // ---- prologue: Q + K0 + V0 (64 rows x 16 chunks each, 8 per thread) ----
    #pragma unroll
    for (int it = 0; it < 8; it++) {
        int i = it * THREADS + tid;
        int r = i >> 4, c = i & 15;
        cp16(sb + 2 * (SQ_H + r * QS + c * 8), qg + (size_t)r * DDIM + c * 8);
    }
    {
        const __half* kg = Th + (size_t)b * SLEN * DDIM;
        const __half* vg = Vh + (size_t)b * SLEN * DDIM;
        #pragma unroll
        for (int it = 0; it < 8; it++) {
            int i = it * THREADS + tid;
            int r = i >> 4, c = i & 15;
            cp16(sb + 2 * (SK0_H + r * KS + c * 8), kg + (size_t)r * DDIM + c * 8);
            cp16(sb + 2 * (SV0_H + r * VS + c * 8), vg + (size_t)r * DDIM + c * 8);
        }
    }
    CP_COMMIT();

    float Oa[16][4];
    #pragma unroll
    for (int nt = 0; nt < 16; nt++)
        #pragma unroll
        for (int k = 0; k < 4; k++) Oa[nt][k] = 0.0f;
    float rslo = 0.0f, rshi = 0.0f;

    const int nkt = qt + 1;
    for (int kt = 0; kt < nkt; kt++) {
        const int bf = kt & 1;
        CP_WAIT0();
        __syncthreads();    // K/V(kt) published; all warps done reading bf^1 buffers

        // ---- prefetch kt+1 ----
        if (kt + 1 < nkt) {
            const uint32_t skb = sb + 2 * ((bf ^ 1) ? SK1_H : SK0_H);
            const uint32_t svb = sb + 2 * ((bf ^ 1) ? SV1_H : SV0_H);
            const __half* kg = Th + ((size_t)b * SLEN + (size_t)(kt + 1) * TK) * DDIM;
            const __half* vg = Vh + ((size_t)b * SLEN + (size_t)(kt + 1) * TK) * DDIM;
            #pragma unroll
            for (int it = 0; it < 8; it++) {
                int i = it * THREADS + tid;
                int r = i >> 4, c = i & 15;
                cp16(skb + 2 * (r * KS + c * 8), kg + (size_t)r * DDIM + c * 8);
                cp16(svb + 2 * (r * VS + c * 8), vg + (size_t)r * DDIM + c * 8);
            }
        }
        CP_COMMIT();

        // ---- QK^T (warp tile 16x64, fp32 accum) ----
        float S[8][4];
        #pragma unroll
        for (int nt = 0; nt < 8; nt++)
            #pragma unroll
            for (int k = 0; k < 4; k++) S[nt][k] = 0.0f;

        #pragma unroll
        for (int ks = 0; ks < 8; ks++) {
            const uint32_t ko = 32u * ks;    // 16 halves per k-step
            uint32_t a0, a1, a2, a3;
            ldsm4(a0, a1, a2, a3, qa + ko);
            #pragma unroll
            for (int p = 0; p < 4; p++) {
                uint32_t r0, r1, r2, r3;
                ldsm4(r0, r1, r2, r3, kb[bf][p] + ko);
                mma16(S[2 * p + 0], a0, a1, a2, a3, r0, r2);
                mma16(S[2 * p + 1], a0, a1, a2, a3, r1, r3);
            }
        }

        // ---- epilogue: threshold + causal + f16x2 exp2 -> register-resident P ----
        const bool diag = (kt == qt);
        const int grlo = qt * TQ + wr + lq;
        const int grhi = grlo + 8;
        uint32_t pl[8], ph[8];
        __half2 accLo = __float2half2_rn(0.0f);
        __half2 accHi = __float2half2_rn(0.0f);
        #pragma unroll
        for (int nt = 0; nt < 8; nt++) {
            const int c = nt * 8 + lr * 2;
            const int gc = kt * TK + c;
            float l0 = (S[nt][0] > 0.3f) ? S[nt][0] * CEX : 0.0f;
            float l1 = (S[nt][1] > 0.3f) ? S[nt][1] * CEX : 0.0f;
            float l2 = (S[nt][2] > 0.3f) ? S[nt][2] * CEX : 0.0f;
            float l3 = (S[nt][3] > 0.3f) ? S[nt][3] * CEX : 0.0f;
            if (diag) {
                if (gc     > grlo) l0 = BIGN;
                if (gc + 1 > grlo) l1 = BIGN;
                if (gc     > grhi) l2 = BIGN;
                if (gc + 1 > grhi) l3 = BIGN;
            }
            __half2 hlo = __floats2half2_rn(l0, l1);
            __half2 hhi = __floats2half2_rn(l2, l3);
            pl[nt] = ex2h2(*(uint32_t*)&hlo);
            ph[nt] = ex2h2(*(uint32_t*)&hhi);
            accLo = __hadd2(accLo, *(__half2*)&pl[nt]);
            accHi = __hadd2(accHi, *(__half2*)&ph[nt]);
        }
        {
            float2 fl = __half22float2(accLo);
            float2 fh = __half22float2(accHi);
            rslo += fl.x + fl.y;
            rshi += fh.x + fh.y;
        }

        // ---- PV: A = register P fragments, B = V via ldmatrix.trans ----
        // a0=(r,c) a1=(r+8,c) a2=(r,c+8) a3=(r+8,c+8): pl/ph[2ks], pl/ph[2ks+1]
        #pragma unroll
        for (int ks = 0; ks < 4; ks++) {
            const uint32_t ko = 4352u * ks;   // 16 k-rows * 136 halves * 2B
            const uint32_t a0 = pl[2 * ks], a1 = ph[2 * ks];
            const uint32_t a2 = pl[2 * ks + 1], a3 = ph[2 * ks + 1];
            #pragma unroll
            for (int p = 0; p < 8; p++) {
                uint32_t r0, r1, r2, r3;
                ldsm4t(r0, r1, r2, r3, vb[bf] + ko + 32u * p);
                mma16(Oa[2 * p + 0], a0, a1, a2, a3, r0, r1);
                mma16(Oa[2 * p + 1], a0, a1, a2, a3, r2, r3);
            }
        }
    }

    // ---- rowsum reduce within quad (warp-exclusive rows, no smem) ----
    rslo += __shfl_xor_sync(0xffffffffu, rslo, 1);
    rslo += __shfl_xor_sync(0xffffffffu, rslo, 2);
    rshi += __shfl_xor_sync(0xffffffffu, rshi, 1);
    rshi += __shfl_xor_sync(0xffffffffu, rshi, 2);
    const float invlo = 1.0f / rslo;
    const float invhi = 1.0f / rshi;

    // ---- normalize + store ----
    float* outb = Og + ((size_t)b * SLEN + (size_t)qt * TQ) * DDIM;
    const int rlo = wr + lq;
    const int rhi = rlo + 8;
    #pragma unroll
    for (int nt = 0; nt < 16; nt++) {
        const int c = nt * 8 + lr * 2;
        *(float2*)(outb + (size_t)rlo * DDIM + c) =
            make_float2(Oa[nt][0] * invlo, Oa[nt][1] * invlo);
        *(float2*)(outb + (size_t)rhi * DDIM + c) =
            make_float2(Oa[nt][2] * invhi, Oa[nt][3] * invhi);
    }
}

extern "C" void kernel_launch(void* const* d_in, const int* in_sizes, int n_in,
                              void* d_out, int out_size) {
    (void)in_sizes; (void)n_in; (void)out_size;
    const float* Q = (const float*)d_in[0];
    const float* T = (const float*)d_in[1];
    const float* V = (const float*)d_in[2];
    float* O = (float*)d_out;

    __half *qh, *th, *vh;
    cudaGetSymbolAddress((void**)&qh, g_Qh);
    cudaGetSymbolAddress((void**)&th, g_Th);
    cudaGetSymbolAddress((void**)&vh, g_Vh);

    const int n4 = NB * SLEN * DDIM / 4;
    dim3 cgrid(n4 / 256, 3);
    convAll<<<cgrid, 256>>>(Q, T, V, qh, th, vh);

    cudaFuncSetAttribute(attn_h, cudaFuncAttributeMaxDynamicSharedMemorySize, SMEM_BYTES);
    attn_h<<<(SLEN / TQ) * NB, THREADS, SMEM_BYTES>>>(qh, th, vh, O);
}